// round 11
// baseline (speedup 1.0000x reference)
#include <cuda_runtime.h>
#include <cuda_fp16.h>
#include <cstdint>

#define HW 4096
#define DDIM 64
#define NSLICE 256          // total K slices of 16
#define QSLICE 64           // slices per K-quarter (per warp)
#define NBLKQ 32            // 32-wide K blocks per quarter
#define TM 32               // rows per CTA

// B fragments, lane-major: g_fp[slice][q][lane][4 x b32]; uint4 index = s*128 + q*32 + l
// ISA->real K map (per 32-block, full-line A loads): real = 8*(l&3) + 4*(s&1) + 2*pair + t
__device__ uint32_t g_fp[NSLICE * 4 * 32 * 4];

// ---------------------------------------------------------------------------
// Kernel 1: build packed B fragments of f[m,d] = cos(8pi*(w0*gx + w1*gy + b))
// ---------------------------------------------------------------------------
__global__ void pos_enc_kernel(const float* __restrict__ w,
                               const float* __restrict__ bias) {
    int idx = blockIdx.x * blockDim.x + threadIdx.x;
    if (idx >= NSLICE * 512) return;
    int c    = idx & 3;        // uint4 component
    int l    = (idx >> 2) & 31;
    int q    = (idx >> 7) & 3;
    int gs   = idx >> 9;       // global slice
    int j    = q * 2 + (c >> 1);
    int pair = c & 1;
    int d    = j * 8 + (l >> 2);
    int m0   = (gs >> 1) * 32 + ((l & 3) << 3) + ((gs & 1) << 2) + (pair << 1);
    float w0 = w[2 * d], w1 = w[2 * d + 1], bd = bias[d];
    float v[2];
#pragma unroll
    for (int t = 0; t < 2; t++) {
        int m = m0 + t;
        int x = m & 63, y = m >> 6;
        float gx = (float)(2 * x - 63) * (1.0f / 64.0f);
        float gy = (float)(2 * y - 63) * (1.0f / 64.0f);
        v[t] = cosf(25.132741228718345f * fmaf(w0, gx, fmaf(w1, gy, bd)));
    }
    __half2 h = __floats2half2_rn(v[0], v[1]);
    g_fp[idx] = *reinterpret_cast<uint32_t*>(&h);
}

// ---------------------------------------------------------------------------
static __device__ __forceinline__ uint32_t e2p(float a, float b) {
    __half2 h = __floats2half2_rn(__expf(a), __expf(b));
    return *reinterpret_cast<uint32_t*>(&h);
}

#define MMA(dst, a0, a1, a2, a3, b0, b1)                                        \
    asm volatile("mma.sync.aligned.m16n8k16.row.col.f32.f16.f16.f32 "           \
                 "{%0,%1,%2,%3},{%4,%5,%6,%7},{%8,%9},{%0,%1,%2,%3};"           \
                 : "+f"(dst[0]), "+f"(dst[1]), "+f"(dst[2]), "+f"(dst[3])       \
                 : "r"(a0), "r"(a1), "r"(a2), "r"(a3), "r"(b0), "r"(b1))

// Load one 32-wide K block (full 128B lines): rows l/4 and l/4+8, 32B each
#define LA(b)                                                                   \
    do { const float* _p = pA + (size_t)(b) * 32;                               \
        R[0] = __ldcs((const float4*)_p);                                       \
        R[1] = __ldcs((const float4*)(_p + 4));                                 \
        R[2] = __ldcs((const float4*)(_p + 8 * HW));                            \
        R[3] = __ldcs((const float4*)(_p + 8 * HW + 4)); } while (0)

// 9 MMAs of one 16-slice against on-demand B
#define SLICE_MMAS(sidx, a0, a1, a2, a3)                                        \
    do {                                                                        \
        const uint4* _bp = pB + (size_t)(sidx) * 128;                           \
        uint4 B0 = __ldg(_bp);      uint4 B1 = __ldg(_bp + 32);                 \
        uint4 B2 = __ldg(_bp + 64); uint4 B3 = __ldg(_bp + 96);                 \
        MMA(acc[0], a0, a1, a2, a3, B0.x, B0.y);                                \
        MMA(acc[1], a0, a1, a2, a3, B0.z, B0.w);                                \
        MMA(acc[2], a0, a1, a2, a3, B1.x, B1.y);                                \
        MMA(acc[3], a0, a1, a2, a3, B1.z, B1.w);                                \
        MMA(acc[4], a0, a1, a2, a3, B2.x, B2.y);                                \
        MMA(acc[5], a0, a1, a2, a3, B2.z, B2.w);                                \
        MMA(acc[6], a0, a1, a2, a3, B3.x, B3.y);                                \
        MMA(acc[7], a0, a1, a2, a3, B3.z, B3.w);                                \
        MMA(acc[8], a0, a1, a2, a3, bz, bz);                                    \
    } while (0)

// Block stage: pack-early (frees R), prefetch next block, 18 MMAs
#define STAGE(b)                                                                \
    do {                                                                        \
        uint32_t p00 = e2p(R[0].x, R[0].y), p01 = e2p(R[0].z, R[0].w);          \
        uint32_t p02 = e2p(R[2].x, R[2].y), p03 = e2p(R[2].z, R[2].w);          \
        uint32_t p10 = e2p(R[1].x, R[1].y), p11 = e2p(R[1].z, R[1].w);          \
        uint32_t p12 = e2p(R[3].x, R[3].y), p13 = e2p(R[3].z, R[3].w);          \
        if ((b) + 1 < NBLKQ) LA((b) + 1);                                       \
        SLICE_MMAS(2 * (b),     p00, p02, p01, p03);                            \
        SLICE_MMAS(2 * (b) + 1, p10, p12, p11, p13);                            \
    } while (0)

struct SmemT {
    float Cs[TM][66];
    float Zs[TM];
    float Zr[TM];
};

// ---------------------------------------------------------------------------
// Kernel 2: 256-thr CTA = 2 row-groups(16) x 4 K-quarters. Warp: 16r x 64N x K=1024.
// Register-direct loads, pack-early single-block A pipeline, Z via 9th MMA.
// Grid 512, launch_bounds(256,3) -> 3 CTAs / 24 warps per SM.
// ---------------------------------------------------------------------------
__global__ __launch_bounds__(256, 3)
void gp_kernel(const float* __restrict__ sim, float* __restrict__ out) {
    __shared__ SmemT sm;

    const int tid = threadIdx.x;
    const int l   = tid & 31;
    const int w   = tid >> 5;
    const int wm  = w & 1;        // row group (16 rows)
    const int kq  = w >> 1;       // K quarter
    const int bb  = blockIdx.y;
    const int row0 = blockIdx.x * TM;

    const float* pA = sim + ((size_t)bb * HW + row0 + wm * 16 + (l >> 2)) * (size_t)HW
                          + kq * (QSLICE * 16) + (l & 3) * 8;
    const uint4* pB = ((const uint4*)g_fp) + (size_t)kq * QSLICE * 128 + l;

    float acc[9][4];
#pragma unroll
    for (int i = 0; i < 9; i++)
#pragma unroll
        for (int k = 0; k < 4; k++) acc[i][k] = 0.0f;

    const uint32_t bz = (l < 4) ? 0x3C003C00u : 0u;  // ones in B col n=0

    float4 R[4];
    LA(0);

#pragma unroll 1
    for (int b = 0; b < NBLKQ; b += 2) {
        STAGE(b);
        STAGE(b + 1);
    }

    // ---- epilogue: merge 4 K-quarters via smem, divide by Z, store ----
    const int lr = wm * 16 + (l >> 2);
    if (kq == 0) {
#pragma unroll
        for (int j = 0; j < 8; j++) {
            const int c0 = j * 8 + (l & 3) * 2;
            *(float2*)&sm.Cs[lr][c0]     = make_float2(acc[j][0], acc[j][1]);
            *(float2*)&sm.Cs[lr + 8][c0] = make_float2(acc[j][2], acc[j][3]);
        }
        if ((l & 3) == 0) { sm.Zs[lr] = acc[8][0]; sm.Zs[lr + 8] = acc[8][2]; }
    }
#pragma unroll
    for (int q = 1; q < 4; q++) {
        __syncthreads();
        if (kq == q) {
#pragma unroll
            for (int j = 0; j < 8; j++) {
                const int c0 = j * 8 + (l & 3) * 2;
                sm.Cs[lr][c0]         += acc[j][0];
                sm.Cs[lr][c0 + 1]     += acc[j][1];
                sm.Cs[lr + 8][c0]     += acc[j][2];
                sm.Cs[lr + 8][c0 + 1] += acc[j][3];
            }
            if ((l & 3) == 0) { sm.Zs[lr] += acc[8][0]; sm.Zs[lr + 8] += acc[8][2]; }
        }
    }
    __syncthreads();
    if (tid < TM) sm.Zr[tid] = 1.0f / sm.Zs[tid];
    __syncthreads();

    {
        const int d = tid >> 2, seg = tid & 3;
        float* go = out + ((size_t)(bb * DDIM + d)) * HW + row0 + seg * 8;
#pragma unroll
        for (int i = 0; i < 2; i++) {
            float4 o;
#pragma unroll
            for (int k = 0; k < 4; k++) {
                const int n = seg * 8 + i * 4 + k;
                (&o.x)[k] = sm.Cs[n][d] * sm.Zr[n];
            }
            *(float4*)(go + i * 4) = o;
        }
    }
}

// ---------------------------------------------------------------------------
extern "C" void kernel_launch(void* const* d_in, const int* in_sizes, int n_in,
                              void* d_out, int out_size) {
    const float* sim  = (const float*)d_in[0];  // [4, 4096, 4096] fp32
    const float* w    = (const float*)d_in[1];  // [64, 2] fp32
    const float* bias = (const float*)d_in[2];  // [64] fp32
    float* out = (float*)d_out;                 // [4, 64, 64, 64] fp32

    pos_enc_kernel<<<(NSLICE * 512 + 255) / 256, 256>>>(w, bias);

    dim3 grid(HW / TM, 4);
    gp_kernel<<<grid, 256>>>(sim, out);
}

// round 12
// speedup vs baseline: 1.3479x; 1.3479x over previous
#include <cuda_runtime.h>
#include <cuda_fp16.h>
#include <cstdint>

#define HW 4096
#define DDIM 64
#define NSLICE 256          // total K slices of 16
#define HSLICE 128          // slices per K-half
#define NBLK 64             // 32-wide K blocks per K-half
#define CHUNK 8             // slices per smem B chunk
#define NCHUNKS (HSLICE / CHUNK)
#define CS_STRIDE 66
#define SMEM_BYTES 65536    // B: [2 half][2 buf][8 slices][2KB]

// B fragments, lane-major: g_fp[slice][q][lane][4 x b32]; uint4 index = s*128 + q*32 + l
// ISA->real K map (per 32-block, full-line A loads): real = 8*(l&3) + 4*(s&1) + 2*pair + t
__device__ uint32_t g_fp[NSLICE * 4 * 32 * 4];

// ---------------------------------------------------------------------------
// Kernel 1: build packed B fragments of f[m,d] = cos(8pi*(w0*gx + w1*gy + b))
// ---------------------------------------------------------------------------
__global__ void pos_enc_kernel(const float* __restrict__ w,
                               const float* __restrict__ bias) {
    int idx = blockIdx.x * blockDim.x + threadIdx.x;
    if (idx >= NSLICE * 512) return;
    int c    = idx & 3;
    int l    = (idx >> 2) & 31;
    int q    = (idx >> 7) & 3;
    int gs   = idx >> 9;
    int j    = q * 2 + (c >> 1);
    int pair = c & 1;
    int d    = j * 8 + (l >> 2);
    int m0   = (gs >> 1) * 32 + ((l & 3) << 3) + ((gs & 1) << 2) + (pair << 1);
    float w0 = w[2 * d], w1 = w[2 * d + 1], bd = bias[d];
    float v[2];
#pragma unroll
    for (int t = 0; t < 2; t++) {
        int m = m0 + t;
        int x = m & 63, y = m >> 6;
        float gx = (float)(2 * x - 63) * (1.0f / 64.0f);
        float gy = (float)(2 * y - 63) * (1.0f / 64.0f);
        v[t] = cosf(25.132741228718345f * fmaf(w0, gx, fmaf(w1, gy, bd)));
    }
    __half2 h = __floats2half2_rn(v[0], v[1]);
    g_fp[idx] = *reinterpret_cast<uint32_t*>(&h);
}

// ---------------------------------------------------------------------------
static __device__ __forceinline__ uint32_t e2p(float a, float b) {
    __half2 h = __floats2half2_rn(__expf(a), __expf(b));
    return *reinterpret_cast<uint32_t*>(&h);
}

#define MMA(dst, a0, a1, a2, a3, b0, b1)                                        \
    asm volatile("mma.sync.aligned.m16n8k16.row.col.f32.f16.f16.f32 "           \
                 "{%0,%1,%2,%3},{%4,%5,%6,%7},{%8,%9},{%0,%1,%2,%3};"           \
                 : "+f"(dst[0]), "+f"(dst[1]), "+f"(dst[2]), "+f"(dst[3])       \
                 : "r"(a0), "r"(a1), "r"(a2), "r"(a3), "r"(b0), "r"(b1))

// Load one 32-wide K block (full 128B lines): rows l/4 and l/4+8, 32B each
#define LA(st, b)                                                               \
    do { const float* _p = pA + (size_t)(b) * 32;                               \
        R[st][0] = __ldcs((const float4*)_p);                                   \
        R[st][1] = __ldcs((const float4*)(_p + 4));                             \
        R[st][2] = __ldcs((const float4*)(_p + 8 * HW));                        \
        R[st][3] = __ldcs((const float4*)(_p + 8 * HW + 4)); } while (0)

// Cooperative cp.async fill of buf p with chunk c (this K-half's 16 KB)
#define FILLB(p, c)                                                             \
    do {                                                                        \
        const char* _s = gBsrc + (size_t)(c) * (CHUNK * 2048) + wg_tid * 16;    \
        uint32_t _d = bhalf + (p) * 16384 + wg_tid * 16;                        \
        _Pragma("unroll")                                                       \
        for (int _j = 0; _j < 8; _j++)                                          \
            asm volatile("cp.async.cg.shared.global [%0], [%1], 16;"            \
                         :: "r"(_d + _j * 2048), "l"(_s + _j * 2048) : "memory");\
        asm volatile("cp.async.commit_group;" ::: "memory");                    \
    } while (0)

// One 16-slice: B from smem (29cyc), exp+Z, A prefetch, 8 MMAs
#define HALF_STAGE(si, rl, rh, do_la, st, blk, p)                               \
    do {                                                                        \
        uint32_t _ba = bhalf + (p) * 16384 + (si) * 2048 + l * 16;              \
        uint4 B0, B1, B2, B3;                                                   \
        asm volatile("ld.shared.v4.u32 {%0,%1,%2,%3}, [%4];"                    \
            : "=r"(B0.x), "=r"(B0.y), "=r"(B0.z), "=r"(B0.w) : "r"(_ba));       \
        asm volatile("ld.shared.v4.u32 {%0,%1,%2,%3}, [%4];"                    \
            : "=r"(B1.x), "=r"(B1.y), "=r"(B1.z), "=r"(B1.w) : "r"(_ba + 512)); \
        asm volatile("ld.shared.v4.u32 {%0,%1,%2,%3}, [%4];"                    \
            : "=r"(B2.x), "=r"(B2.y), "=r"(B2.z), "=r"(B2.w) : "r"(_ba + 1024));\
        asm volatile("ld.shared.v4.u32 {%0,%1,%2,%3}, [%4];"                    \
            : "=r"(B3.x), "=r"(B3.y), "=r"(B3.z), "=r"(B3.w) : "r"(_ba + 1536));\
        float e0 = __expf(rl.x), e1 = __expf(rl.y);                             \
        float e2 = __expf(rl.z), e3 = __expf(rl.w);                             \
        z0 += (e0 + e1) + (e2 + e3);                                            \
        float e4 = __expf(rh.x), e5 = __expf(rh.y);                             \
        float e6 = __expf(rh.z), e7 = __expf(rh.w);                             \
        z1 += (e4 + e5) + (e6 + e7);                                            \
        __half2 h0 = __floats2half2_rn(e0, e1);                                 \
        __half2 h1 = __floats2half2_rn(e2, e3);                                 \
        __half2 h2 = __floats2half2_rn(e4, e5);                                 \
        __half2 h3 = __floats2half2_rn(e6, e7);                                 \
        uint32_t ra0 = *reinterpret_cast<uint32_t*>(&h0);                       \
        uint32_t ra2 = *reinterpret_cast<uint32_t*>(&h1);                       \
        uint32_t ra1 = *reinterpret_cast<uint32_t*>(&h2);                       \
        uint32_t ra3 = *reinterpret_cast<uint32_t*>(&h3);                       \
        if (do_la && (blk) + 2 < NBLK) LA(st, (blk) + 2);                       \
        MMA(acc[0], ra0, ra1, ra2, ra3, B0.x, B0.y);                            \
        MMA(acc[1], ra0, ra1, ra2, ra3, B0.z, B0.w);                            \
        MMA(acc[2], ra0, ra1, ra2, ra3, B1.x, B1.y);                            \
        MMA(acc[3], ra0, ra1, ra2, ra3, B1.z, B1.w);                            \
        MMA(acc[4], ra0, ra1, ra2, ra3, B2.x, B2.y);                            \
        MMA(acc[5], ra0, ra1, ra2, ra3, B2.z, B2.w);                            \
        MMA(acc[6], ra0, ra1, ra2, ra3, B3.x, B3.y);                            \
        MMA(acc[7], ra0, ra1, ra2, ra3, B3.z, B3.w);                            \
    } while (0)

// Block = 2 slices (local i-th block in chunk); A double-buffer st
#define STAGE(st, blk, i, p)                                                    \
    do {                                                                        \
        HALF_STAGE(2 * (i),     R[st][0], R[st][2], 0, st, blk, p);             \
        HALF_STAGE(2 * (i) + 1, R[st][1], R[st][3], 1, st, blk, p);             \
    } while (0)

// ---------------------------------------------------------------------------
// Kernel 2: 8 warps = 4 row-groups x 2 K-halves. Warp: 16 rows x 64 N x K=2048.
// B double-buffered in smem via cp.async (1 copy/CTA, 29-cyc reads);
// full-line register A pipeline (dist 4 slices); Z via FADD + shuffle.
// ---------------------------------------------------------------------------
__global__ __launch_bounds__(256, 2)
void gp_kernel(const float* __restrict__ sim, float* __restrict__ out) {
    extern __shared__ char smem[];
    uint32_t smem_u;
    asm("{ .reg .u64 t; cvta.to.shared.u64 t, %1; cvt.u32.u64 %0, t; }"
        : "=r"(smem_u) : "l"(smem));

    const int tid    = threadIdx.x;
    const int l      = tid & 31;
    const int w      = tid >> 5;
    const int wm     = w & 3;        // row group
    const int kh     = w >> 2;       // K half
    const int wg_tid = tid & 127;
    const int bb     = blockIdx.y;
    const int row0   = blockIdx.x * 64;

    const float* pA = sim + ((size_t)bb * HW + row0 + wm * 16 + (l >> 2)) * (size_t)HW
                          + kh * (HSLICE * 16) + (l & 3) * 8;
    const char* gBsrc = (const char*)g_fp + (size_t)kh * HSLICE * 2048;
    const uint32_t bhalf = smem_u + kh * 32768;   // this half's 2 buffers

    float acc[8][4];
#pragma unroll
    for (int i = 0; i < 8; i++)
#pragma unroll
        for (int k = 0; k < 4; k++) acc[i][k] = 0.0f;

    float z0 = 0.0f, z1 = 0.0f;

    float4 R[2][4];
    LA(0, 0); LA(1, 1);
    FILLB(0, 0);
    asm volatile("cp.async.wait_group 0;" ::: "memory");
    __syncthreads();

    int b = 0;
#pragma unroll 1
    for (int c = 0; c < NCHUNKS; c++) {
        const int p = c & 1;
        if (c + 1 < NCHUNKS) FILLB(p ^ 1, c + 1);
        STAGE(0, b,     0, p);
        STAGE(1, b + 1, 1, p);
        STAGE(0, b + 2, 2, p);
        STAGE(1, b + 3, 3, p);
        b += 4;
        asm volatile("cp.async.wait_group 0;" ::: "memory");
        __syncthreads();
    }

    // ---- epilogue: Z quad-reduce, merge K-halves via smem, divide, store ----
    z0 += __shfl_xor_sync(0xFFFFFFFFu, z0, 1);
    z0 += __shfl_xor_sync(0xFFFFFFFFu, z0, 2);
    z1 += __shfl_xor_sync(0xFFFFFFFFu, z1, 1);
    z1 += __shfl_xor_sync(0xFFFFFFFFu, z1, 2);

    float* Cs = (float*)smem;                        // [64][CS_STRIDE]
    float* Zs = (float*)(smem + 64 * CS_STRIDE * 4);
    float* Zr = Zs + 64;

    const int lr = wm * 16 + (l >> 2);
    if (kh == 0) {
#pragma unroll
        for (int j = 0; j < 8; j++) {
            const int c0 = j * 8 + (l & 3) * 2;
            *(float2*)&Cs[lr * CS_STRIDE + c0]       = make_float2(acc[j][0], acc[j][1]);
            *(float2*)&Cs[(lr + 8) * CS_STRIDE + c0] = make_float2(acc[j][2], acc[j][3]);
        }
        if ((l & 3) == 0) { Zs[lr] = z0; Zs[lr + 8] = z1; }
    }
    __syncthreads();
    if (kh == 1) {
#pragma unroll
        for (int j = 0; j < 8; j++) {
            const int c0 = j * 8 + (l & 3) * 2;
            Cs[lr * CS_STRIDE + c0]           += acc[j][0];
            Cs[lr * CS_STRIDE + c0 + 1]       += acc[j][1];
            Cs[(lr + 8) * CS_STRIDE + c0]     += acc[j][2];
            Cs[(lr + 8) * CS_STRIDE + c0 + 1] += acc[j][3];
        }
        if ((l & 3) == 0) { Zs[lr] += z0; Zs[lr + 8] += z1; }
    }
    __syncthreads();
    if (tid < 64) Zr[tid] = 1.0f / Zs[tid];
    __syncthreads();

    {
        const int d = tid >> 2, seg = tid & 3;
        float* go = out + ((size_t)(bb * DDIM + d)) * HW + row0 + seg * 16;
#pragma unroll
        for (int i = 0; i < 4; i++) {
            const int n = seg * 16 + i * 4;
            float4 o;
            o.x = Cs[(n + 0) * CS_STRIDE + d] * Zr[n + 0];
            o.y = Cs[(n + 1) * CS_STRIDE + d] * Zr[n + 1];
            o.z = Cs[(n + 2) * CS_STRIDE + d] * Zr[n + 2];
            o.w = Cs[(n + 3) * CS_STRIDE + d] * Zr[n + 3];
            *(float4*)(go + i * 4) = o;
        }
    }
}

// ---------------------------------------------------------------------------
extern "C" void kernel_launch(void* const* d_in, const int* in_sizes, int n_in,
                              void* d_out, int out_size) {
    const float* sim  = (const float*)d_in[0];  // [4, 4096, 4096] fp32
    const float* w    = (const float*)d_in[1];  // [64, 2] fp32
    const float* bias = (const float*)d_in[2];  // [64] fp32
    float* out = (float*)d_out;                 // [4, 64, 64, 64] fp32

    cudaFuncSetAttribute(gp_kernel, cudaFuncAttributeMaxDynamicSharedMemorySize, SMEM_BYTES);

    pos_enc_kernel<<<(NSLICE * 512 + 255) / 256, 256>>>(w, bias);

    dim3 grid(HW / 64, 4);
    gp_kernel<<<grid, 256, SMEM_BYTES>>>(sim, out);
}

// round 13
// speedup vs baseline: 1.4604x; 1.0835x over previous
#include <cuda_runtime.h>
#include <cuda_fp16.h>
#include <cstdint>

#define HW 4096
#define DDIM 64
#define NSLICE 256          // total K slices of 16
#define HSLICE 128          // slices per K-half
#define NBLK 64             // 32-wide K blocks per K-half
#define CS_STRIDE 66

// B fragments, lane-major: g_fp[slice][q][lane][4 x b32]; uint4 index = s*128 + q*32 + l
// ISA->real K map (per 32-block, full-line A loads): real = 8*(l&3) + 4*(s&1) + 2*pair + t
__device__ uint32_t g_fp[NSLICE * 4 * 32 * 4];

// ---------------------------------------------------------------------------
// Kernel 1: build packed B fragments of f[m,d] = cos(8pi*(w0*gx + w1*gy + b))
// ---------------------------------------------------------------------------
__global__ void pos_enc_kernel(const float* __restrict__ w,
                               const float* __restrict__ bias) {
    int idx = blockIdx.x * blockDim.x + threadIdx.x;
    if (idx >= NSLICE * 512) return;
    int c    = idx & 3;        // uint4 component
    int l    = (idx >> 2) & 31;
    int q    = (idx >> 7) & 3;
    int gs   = idx >> 9;       // slice
    int j    = q * 2 + (c >> 1);
    int pair = c & 1;
    int d    = j * 8 + (l >> 2);
    int m0   = (gs >> 1) * 32 + ((l & 3) << 3) + ((gs & 1) << 2) + (pair << 1);
    float w0 = w[2 * d], w1 = w[2 * d + 1], bd = bias[d];
    float v[2];
#pragma unroll
    for (int t = 0; t < 2; t++) {
        int m = m0 + t;
        int x = m & 63, y = m >> 6;
        float gx = (float)(2 * x - 63) * (1.0f / 64.0f);
        float gy = (float)(2 * y - 63) * (1.0f / 64.0f);
        v[t] = cosf(25.132741228718345f * fmaf(w0, gx, fmaf(w1, gy, bd)));
    }
    __half2 h = __floats2half2_rn(v[0], v[1]);
    g_fp[idx] = *reinterpret_cast<uint32_t*>(&h);
}

// ---------------------------------------------------------------------------
// exp(x),exp(y) packed in fp16 via ex2.approx.f16x2: lo = exp(x), hi = exp(y).
// cvt.rn.f16x2.f32 d, a, b packs d.hi = a, d.lo = b.
#define E2PH(dst, x, y)                                                         \
    do {                                                                        \
        float _fa = (x) * 1.4426950408889634f;                                  \
        float _fb = (y) * 1.4426950408889634f;                                  \
        asm("cvt.rn.f16x2.f32 %0, %1, %2;" : "=r"(dst) : "f"(_fb), "f"(_fa));   \
        asm("ex2.approx.f16x2 %0, %0;" : "+r"(dst));                            \
    } while (0)

#define MMA(dst, a0, a1, a2, a3, b0, b1)                                        \
    asm volatile("mma.sync.aligned.m16n8k16.row.col.f32.f16.f16.f32 "           \
                 "{%0,%1,%2,%3},{%4,%5,%6,%7},{%8,%9},{%0,%1,%2,%3};"           \
                 : "+f"(dst[0]), "+f"(dst[1]), "+f"(dst[2]), "+f"(dst[3])       \
                 : "r"(a0), "r"(a1), "r"(a2), "r"(a3), "r"(b0), "r"(b1))

// Load one 32-wide K block (full 128B lines): rows l/4 and l/4+8, 32B each
#define LA(st, b)                                                               \
    do { const float* _p = pA + (size_t)(b) * 32;                               \
        R[st][0] = __ldcs((const float4*)_p);                                   \
        R[st][1] = __ldcs((const float4*)(_p + 4));                             \
        R[st][2] = __ldcs((const float4*)(_p + 8 * HW));                        \
        R[st][3] = __ldcs((const float4*)(_p + 8 * HW + 4)); } while (0)

// One 16-slice: on-demand B, f16x2 exp, 9 MMAs. rl/rh = float4 pair (row lo/hi)
#define HALF_STAGE(sidx, rl, rh, do_la, st, blk)                                \
    do {                                                                        \
        const uint4* _bp = pB + (size_t)(sidx) * 128;                           \
        uint4 B0 = __ldg(_bp);      uint4 B1 = __ldg(_bp + 32);                 \
        uint4 B2 = __ldg(_bp + 64); uint4 B3 = __ldg(_bp + 96);                 \
        uint32_t ra0, ra1, ra2, ra3;                                            \
        E2PH(ra0, rl.x, rl.y);                                                  \
        E2PH(ra2, rl.z, rl.w);                                                  \
        E2PH(ra1, rh.x, rh.y);                                                  \
        E2PH(ra3, rh.z, rh.w);                                                  \
        if (do_la && (blk) + 2 < NBLK) LA(st, (blk) + 2);                       \
        MMA(acc[0], ra0, ra1, ra2, ra3, B0.x, B0.y);                            \
        MMA(acc[1], ra0, ra1, ra2, ra3, B0.z, B0.w);                            \
        MMA(acc[2], ra0, ra1, ra2, ra3, B1.x, B1.y);                            \
        MMA(acc[3], ra0, ra1, ra2, ra3, B1.z, B1.w);                            \
        MMA(acc[4], ra0, ra1, ra2, ra3, B2.x, B2.y);                            \
        MMA(acc[5], ra0, ra1, ra2, ra3, B2.z, B2.w);                            \
        MMA(acc[6], ra0, ra1, ra2, ra3, B3.x, B3.y);                            \
        MMA(acc[7], ra0, ra1, ra2, ra3, B3.z, B3.w);                            \
        MMA(acc[8], ra0, ra1, ra2, ra3, bz, bz);                                \
    } while (0)

// Block stage: slice 2b uses R[st][0]/R[st][2]; slice 2b+1 uses R[st][1]/R[st][3]
#define STAGE(st, blk)                                                          \
    do {                                                                        \
        HALF_STAGE(2 * (blk),     R[st][0], R[st][2], 0, st, blk);              \
        HALF_STAGE(2 * (blk) + 1, R[st][1], R[st][3], 1, st, blk);              \
    } while (0)

// ---------------------------------------------------------------------------
// Kernel 2: 8 warps = 4 row-groups x 2 K-halves. Warp: 16 rows x 64 N x K=2048.
// Full-line A loads, on-demand B, f16x2 exp (half the MUFU ops), Z via 9th MMA.
// No smem/barriers in mainloop.
// ---------------------------------------------------------------------------
__global__ __launch_bounds__(256, 2)
void gp_kernel(const float* __restrict__ sim, float* __restrict__ out) {
    __shared__ float Cs[64][CS_STRIDE];
    __shared__ float Zs[64];
    __shared__ float Zr[64];

    const int tid = threadIdx.x;
    const int l   = tid & 31;
    const int w   = tid >> 5;
    const int wm  = w & 3;       // row group
    const int kh  = w >> 2;      // K half
    const int bb  = blockIdx.y;
    const int row0 = blockIdx.x * 64;

    const float* pA = sim + ((size_t)bb * HW + row0 + wm * 16 + (l >> 2)) * (size_t)HW
                          + kh * (HSLICE * 16) + (l & 3) * 8;
    const uint4* pB = ((const uint4*)g_fp) + (size_t)kh * HSLICE * 128 + l;

    float acc[9][4];
#pragma unroll
    for (int i = 0; i < 9; i++)
#pragma unroll
        for (int k = 0; k < 4; k++) acc[i][k] = 0.0f;

    const uint32_t bz = (l < 4) ? 0x3C003C00u : 0u;  // ones in B col n=0

    float4 R[2][4];
    LA(0, 0); LA(1, 1);

#pragma unroll 1
    for (int b = 0; b < NBLK; b += 2) {
        STAGE(0, b);
        STAGE(1, b + 1);
    }

    // ---- epilogue: merge K-halves via smem, divide by Z, coalesced store ----
    const int lr = wm * 16 + (l >> 2);
    if (kh == 0) {
#pragma unroll
        for (int j = 0; j < 8; j++) {
            const int c0 = j * 8 + (l & 3) * 2;
            *(float2*)&Cs[lr][c0]     = make_float2(acc[j][0], acc[j][1]);
            *(float2*)&Cs[lr + 8][c0] = make_float2(acc[j][2], acc[j][3]);
        }
        if ((l & 3) == 0) { Zs[lr] = acc[8][0]; Zs[lr + 8] = acc[8][2]; }
    }
    __syncthreads();
    if (kh == 1) {
#pragma unroll
        for (int j = 0; j < 8; j++) {
            const int c0 = j * 8 + (l & 3) * 2;
            Cs[lr][c0]         += acc[j][0];
            Cs[lr][c0 + 1]     += acc[j][1];
            Cs[lr + 8][c0]     += acc[j][2];
            Cs[lr + 8][c0 + 1] += acc[j][3];
        }
        if ((l & 3) == 0) { Zs[lr] += acc[8][0]; Zs[lr + 8] += acc[8][2]; }
    }
    __syncthreads();
    if (tid < 64) Zr[tid] = 1.0f / Zs[tid];
    __syncthreads();

    {
        const int d = tid >> 2, seg = tid & 3;
        float* go = out + ((size_t)(bb * DDIM + d)) * HW + row0 + seg * 16;
#pragma unroll
        for (int i = 0; i < 4; i++) {
            const int n = seg * 16 + i * 4;
            float4 o;
            o.x = Cs[n + 0][d] * Zr[n + 0];
            o.y = Cs[n + 1][d] * Zr[n + 1];
            o.z = Cs[n + 2][d] * Zr[n + 2];
            o.w = Cs[n + 3][d] * Zr[n + 3];
            *(float4*)(go + i * 4) = o;
        }
    }
}

// ---------------------------------------------------------------------------
extern "C" void kernel_launch(void* const* d_in, const int* in_sizes, int n_in,
                              void* d_out, int out_size) {
    const float* sim  = (const float*)d_in[0];  // [4, 4096, 4096] fp32
    const float* w    = (const float*)d_in[1];  // [64, 2] fp32
    const float* bias = (const float*)d_in[2];  // [64] fp32
    float* out = (float*)d_out;                 // [4, 64, 64, 64] fp32

    pos_enc_kernel<<<(NSLICE * 512 + 255) / 256, 256>>>(w, bias);

    dim3 grid(HW / 64, 4);
    gp_kernel<<<grid, 256>>>(sim, out);
}